// round 10
// baseline (speedup 1.0000x reference)
#include <cuda_runtime.h>
#include <cuda_bf16.h>
#include <cstdint>

#define NN 50000
#define EE 800000
#define GG 512
#define CC 128
#define NBLK 196          // ceil(NN/256) scan blocks

// ---------------- scratch (static device arrays; no allocation) ----------------
__device__ float g_h0[NN*CC];
__device__ float g_h1[NN*CC];
__device__ float g_t1[NN*CC];
__device__ float g_t2[NN*CC];
__device__ float g_dis[NN];
__device__ int   g_hist[NN];
__device__ int   g_ptr[NN+1];
__device__ int   g_fill[NN];
__device__ int   g_bsum[NBLK];
__device__ int2  g_epk[EE];          // packed CSR: (col, bits(norm))
__device__ float g_pool[GG*CC];
__device__ float g_cnt[GG];
__device__ float g_chstat[2*CC];     // [0:128) sum, [128:256) sumsq
__device__ float g_bna[CC];
__device__ float g_bnb[CC];
// split-bf16 weight matrices, B[n][k] layout (transposed, folded), 128 x 384
__device__ __align__(16) __nv_bfloat16 g_Bh[CC*384];
__device__ __align__(16) __nv_bfloat16 g_Bl[CC*384];

// ---------------- mma.sync helpers (baseline PTX, works at compute_103) --------
__device__ __forceinline__ void ldsm4(uint32_t* r, uint32_t addr) {
    asm volatile("ldmatrix.sync.aligned.m8n8.x4.shared.b16 {%0,%1,%2,%3}, [%4];"
                 : "=r"(r[0]), "=r"(r[1]), "=r"(r[2]), "=r"(r[3]) : "r"(addr));
}
__device__ __forceinline__ void mma16816(float* c, const uint32_t* a, const uint32_t* b) {
    asm volatile("mma.sync.aligned.m16n8k16.row.col.f32.bf16.bf16.f32 "
                 "{%0,%1,%2,%3}, {%4,%5,%6,%7}, {%8,%9}, {%0,%1,%2,%3};"
                 : "+f"(c[0]), "+f"(c[1]), "+f"(c[2]), "+f"(c[3])
                 : "r"(a[0]), "r"(a[1]), "r"(a[2]), "r"(a[3]), "r"(b[0]), "r"(b[1]));
}
__device__ __forceinline__ uint32_t smem_u32(const void* p) {
    uint32_t a;
    asm("{ .reg .u64 t; cvta.to.shared.u64 t, %1; cvt.u32.u64 %0, t; }" : "=r"(a) : "l"(p));
    return a;
}

// ---------------- small utility kernels ----------------
__global__ void k_zero4(float* __restrict__ p, int n4) {
    int i = blockIdx.x * blockDim.x + threadIdx.x;
    if (i < n4) ((float4*)p)[i] = make_float4(0.f, 0.f, 0.f, 0.f);
}

// ---------------- CSR build ----------------
__global__ void k_hist(const int* __restrict__ row) {
    int e = blockIdx.x * blockDim.x + threadIdx.x;
    if (e < EE) atomicAdd(&g_hist[row[e]], 1);
}

// fused: per-node dis + per-block sums of hist
__global__ void k_disbsum() {
    __shared__ int sh[256];
    int t = threadIdx.x;
    int n = blockIdx.x * 256 + t;
    int h = (n < NN) ? g_hist[n] : 0;
    if (n < NN) g_dis[n] = (h > 0) ? rsqrtf((float)h) : 0.f;
    sh[t] = h;
    __syncthreads();
    for (int s = 128; s > 0; s >>= 1) {
        if (t < s) sh[t] += sh[t + s];
        __syncthreads();
    }
    if (t == 0) g_bsum[blockIdx.x] = sh[0];
}

// fused: every block scans all block sums in smem, then local scan -> offsets
__global__ void k_offsets() {
    __shared__ int sb[256];
    __shared__ int sh[256];
    int t = threadIdx.x;
    int bv = (t < NBLK) ? g_bsum[t] : 0;
    sb[t] = bv;
    __syncthreads();
    for (int o = 1; o < 256; o <<= 1) {
        int x = (t >= o) ? sb[t - o] : 0;
        __syncthreads();
        sb[t] += x;
        __syncthreads();
    }
    int base = (blockIdx.x == 0) ? 0 : sb[blockIdx.x - 1];   // inclusive scan
    int n = blockIdx.x * 256 + t;
    int v = (n < NN) ? g_hist[n] : 0;
    sh[t] = v;
    __syncthreads();
    for (int o = 1; o < 256; o <<= 1) {
        int x = (t >= o) ? sh[t - o] : 0;
        __syncthreads();
        sh[t] += x;
        __syncthreads();
    }
    int off = base + sh[t] - v;
    if (n < NN) { g_ptr[n] = off; g_fill[n] = off; }
    if (n == NN - 1) g_ptr[NN] = off + v;
}

__global__ void k_scatter(const int* __restrict__ row, const int* __restrict__ col) {
    int e = blockIdx.x * blockDim.x + threadIdx.x;
    if (e >= EE) return;
    int r = row[e], c = col[e];
    int pos = atomicAdd(&g_fill[r], 1);
    float w = -(g_dis[r] * g_dis[c]);
    g_epk[pos] = make_int2(c, __float_as_int(w));
}

// gather-SpMV: dst[r] = sum_j norm_j * src[col_j]   (one warp per row, no atomics)
// simple inner loop — compiler schedules gathers across iterations (R7-proven form)
__global__ void __launch_bounds__(256)
k_spmv(const float* __restrict__ src, float* __restrict__ dst) {
    int w = (blockIdx.x * 256 + threadIdx.x) >> 5;
    if (w >= NN) return;
    int lane = threadIdx.x & 31;
    int s = g_ptr[w], e = g_ptr[w + 1];
    float4 acc = make_float4(0.f, 0.f, 0.f, 0.f);
    for (int j = s; j < e; j += 32) {
        int idx = j + lane;
        int2 pk = (idx < e) ? g_epk[idx] : make_int2(0, 0);
        int cnt = min(32, e - j);
        for (int k = 0; k < cnt; k++) {
            int ck = __shfl_sync(0xffffffffu, pk.x, k);
            float wk = __uint_as_float(__shfl_sync(0xffffffffu, (unsigned)pk.y, k));
            float4 v = ((const float4*)(src + (size_t)ck * CC))[lane];
            acc.x = fmaf(wk, v.x, acc.x);
            acc.y = fmaf(wk, v.y, acc.y);
            acc.z = fmaf(wk, v.z, acc.z);
            acc.w = fmaf(wk, v.w, acc.w);
        }
    }
    ((float4*)(dst + (size_t)w * CC))[lane] = acc;
}

// AtomEncoder: h0[n,c] = sum_f atom_emb[f, x[n,f], c]
__global__ void k_embed(const float* __restrict__ emb, const int* __restrict__ x) {
    int n = blockIdx.x;
    __shared__ int xs[9];
    if (threadIdx.x < 9) xs[threadIdx.x] = x[n * 9 + threadIdx.x];
    __syncthreads();
    int c = threadIdx.x;
    float s = 0.f;
#pragma unroll
    for (int f = 0; f < 9; f++)
        s += emb[((f * 119) + xs[f]) * CC + c];
    g_h0[(size_t)n * CC + c] = s;
}

// Build folded, transposed, split-bf16 weights:
//   Bmod[k][n]: k in [0,128)   -> W0[k][n] - W2[k][n]
//               k in [128,256) -> W1[k-128][n]
//               k in [256,384) -> 2*W2[k-256][n]
__global__ void k_prepB(const float* __restrict__ W) {
    int n = blockIdx.x;       // 0..127
    int k = threadIdx.x;      // 0..383
    int blk = k >> 7, ci = k & 127;
    float w;
    if (blk == 0)      w = W[ci * 128 + n] - W[2 * 16384 + ci * 128 + n];
    else if (blk == 1) w = W[16384 + ci * 128 + n];
    else               w = 2.f * W[2 * 16384 + ci * 128 + n];
    __nv_bfloat16 hi = __float2bfloat16(w);
    g_Bh[n * 384 + k] = hi;
    g_Bl[n * 384 + k] = __float2bfloat16(w - __bfloat162float(hi));
}

// mma.sync split-bf16 GEMM: out = relu([A0|A1|A2] @ Bmod^T + bias)
// Block: 128x128 tile. 8 warps (4 M x 2 N), warp tile 32x64.
#define ASTR 144   // smem row stride in bytes (72 bf16, conflict-free for ldmatrix)
__global__ void __launch_bounds__(256)
k_gemm(const float* __restrict__ A0, const float* __restrict__ A1,
       const float* __restrict__ A2, const __nv_bfloat16* __restrict__ Bh_,
       const __nv_bfloat16* __restrict__ Bl_, const float* __restrict__ bias,
       float* __restrict__ out)
{
    extern __shared__ char sm[];
    char* pAH = sm;
    char* pAL = sm + 18432;
    char* pBH = sm + 36864;
    char* pBL = sm + 55296;
    uint32_t sb = smem_u32(sm);
    uint32_t aAH = sb, aAL = sb + 18432, aBH = sb + 36864, aBL = sb + 55296;

    int tid = threadIdx.x;
    int lane = tid & 31, wid = tid >> 5;
    int wm = (wid & 3) * 32;
    int wn = (wid >> 2) * 64;
    int m0 = blockIdx.x * 128;

    float acc[2][8][4];
#pragma unroll
    for (int mi = 0; mi < 2; mi++)
#pragma unroll
        for (int nj = 0; nj < 8; nj++)
#pragma unroll
            for (int q = 0; q < 4; q++) acc[mi][nj][q] = 0.f;

    const float* srcs[3] = {A0, A1, A2};
    const uint2* BhG = (const uint2*)Bh_;
    const uint2* BlG = (const uint2*)Bl_;

    for (int ch = 0; ch < 6; ch++) {
        const float4* S4 = (const float4*)srcs[ch >> 1];
        int k4off = (ch & 1) * 16;
#pragma unroll
        for (int it = 0; it < 8; it++) {
            int idx = it * 256 + tid;
            int r = idx >> 4, kq = idx & 15;
            int rg = m0 + r;
            float4 v = (rg < NN) ? S4[(size_t)rg * 32 + k4off + kq]
                                 : make_float4(0.f, 0.f, 0.f, 0.f);
            __nv_bfloat162 h01 = __floats2bfloat162_rn(v.x, v.y);
            __nv_bfloat162 h23 = __floats2bfloat162_rn(v.z, v.w);
            __nv_bfloat162 l01 = __floats2bfloat162_rn(v.x - __bfloat162float(h01.x),
                                                       v.y - __bfloat162float(h01.y));
            __nv_bfloat162 l23 = __floats2bfloat162_rn(v.z - __bfloat162float(h23.x),
                                                       v.w - __bfloat162float(h23.y));
            int off = r * ASTR + kq * 8;
            *(__nv_bfloat162*)(pAH + off)     = h01;
            *(__nv_bfloat162*)(pAH + off + 4) = h23;
            *(__nv_bfloat162*)(pAL + off)     = l01;
            *(__nv_bfloat162*)(pAL + off + 4) = l23;
        }
        int kbG = ch * 16;
#pragma unroll
        for (int it = 0; it < 8; it++) {
            int idx = it * 256 + tid;
            int n = idx >> 4, kq = idx & 15;
            int off = n * ASTR + kq * 8;
            *(uint2*)(pBH + off) = BhG[n * 96 + kbG + kq];
            *(uint2*)(pBL + off) = BlG[n * 96 + kbG + kq];
        }
        __syncthreads();

#pragma unroll
        for (int ks = 0; ks < 4; ks++) {
            int kb = ks * 16;
            uint32_t ah[2][4], al[2][4], bh[8][2], bl[8][2];
            uint32_t aoff = (uint32_t)((wm + (lane & 15)) * ASTR
                          + (kb + ((lane >> 4) << 3)) * 2);
            ldsm4(ah[0], aAH + aoff);
            ldsm4(ah[1], aAH + aoff + 16 * ASTR);
            ldsm4(al[0], aAL + aoff);
            ldsm4(al[1], aAL + aoff + 16 * ASTR);
            uint32_t boff = (uint32_t)((wn + ((lane >> 4) << 3) + (lane & 7)) * ASTR
                          + (kb + (((lane >> 3) & 1) << 3)) * 2);
#pragma unroll
            for (int p = 0; p < 4; p++) {
                uint32_t r4[4];
                ldsm4(r4, aBH + boff + p * 16 * ASTR);
                bh[2*p][0] = r4[0]; bh[2*p][1] = r4[1];
                bh[2*p+1][0] = r4[2]; bh[2*p+1][1] = r4[3];
                ldsm4(r4, aBL + boff + p * 16 * ASTR);
                bl[2*p][0] = r4[0]; bl[2*p][1] = r4[1];
                bl[2*p+1][0] = r4[2]; bl[2*p+1][1] = r4[3];
            }
#pragma unroll
            for (int mi = 0; mi < 2; mi++)
#pragma unroll
                for (int nj = 0; nj < 8; nj++) {
                    mma16816(acc[mi][nj], ah[mi], bh[nj]);
                    mma16816(acc[mi][nj], ah[mi], bl[nj]);
                    mma16816(acc[mi][nj], al[mi], bh[nj]);
                }
        }
        __syncthreads();
    }

#pragma unroll
    for (int mi = 0; mi < 2; mi++) {
        int r0 = m0 + wm + mi * 16 + (lane >> 2);
#pragma unroll
        for (int nj = 0; nj < 8; nj++) {
            int c = wn + nj * 8 + 2 * (lane & 3);
            float bx = __ldg(bias + c), by = __ldg(bias + c + 1);
            if (r0 < NN) {
                float2 o;
                o.x = fmaxf(acc[mi][nj][0] + bx, 0.f);
                o.y = fmaxf(acc[mi][nj][1] + by, 0.f);
                *(float2*)(out + (size_t)r0 * CC + c) = o;
            }
            if (r0 + 8 < NN) {
                float2 o;
                o.x = fmaxf(acc[mi][nj][2] + bx, 0.f);
                o.y = fmaxf(acc[mi][nj][3] + by, 0.f);
                *(float2*)(out + (size_t)(r0 + 8) * CC + c) = o;
            }
        }
    }
}

// channel sums/sumsq (BN) + per-graph pooling sums + per-graph counts
// (batch sorted -> run accumulation; channel-0 thread also accumulates counts)
__global__ void k_statspool(const float* __restrict__ h, const int* __restrict__ batch) {
    int c = threadIdx.x;
    int base = blockIdx.x * 128;
    float s = 0.f, sq = 0.f, acc = 0.f;
    float cacc = 0.f;
    int cur = -1;
    for (int r = 0; r < 128; r++) {
        int n = base + r;
        if (n >= NN) break;
        int g = batch[n];
        float v = h[(size_t)n * CC + c];
        s += v;
        sq += v * v;
        if (g != cur) {
            if (cur >= 0) {
                atomicAdd(&g_pool[cur * CC + c], acc);
                if (c == 0) atomicAdd(&g_cnt[cur], cacc);
            }
            cur = g;
            acc = 0.f;
            cacc = 0.f;
        }
        acc += v;
        cacc += 1.f;
    }
    if (cur >= 0) {
        atomicAdd(&g_pool[cur * CC + c], acc);
        if (c == 0) atomicAdd(&g_cnt[cur], cacc);
    }
    atomicAdd(&g_chstat[c], s);
    atomicAdd(&g_chstat[CC + c], sq);
}

__global__ void k_bnprep(const float* __restrict__ gamma, const float* __restrict__ beta) {
    int c = threadIdx.x;
    float mu = g_chstat[c] * (1.0f / NN);
    float var = fmaxf(g_chstat[CC + c] * (1.0f / NN) - mu * mu, 0.f);
    float inv = rsqrtf(var + 1e-5f);
    float a = gamma[c] * inv;
    g_bna[c] = a;
    g_bnb[c] = beta[c] - mu * a;
}

__global__ void k_mlp(const float* __restrict__ lw1, const float* __restrict__ lb1,
                      const float* __restrict__ lw2, const float* __restrict__ lb2,
                      float* __restrict__ out) {
    int g = blockIdx.x * blockDim.x + threadIdx.x;
    if (g >= GG) return;
    float inv = 1.0f / fmaxf(g_cnt[g], 1.0f);
    float hid[16];
#pragma unroll
    for (int j = 0; j < 16; j++) hid[j] = lb1[j];
#pragma unroll 4
    for (int c = 0; c < CC; c++) {
        float pb = g_pool[g * CC + c] * inv * g_bna[c] + g_bnb[c];
        const float4* w4 = (const float4*)(lw1 + c * 16);
#pragma unroll
        for (int q = 0; q < 4; q++) {
            float4 w = w4[q];
            hid[q * 4 + 0] += pb * w.x;
            hid[q * 4 + 1] += pb * w.y;
            hid[q * 4 + 2] += pb * w.z;
            hid[q * 4 + 3] += pb * w.w;
        }
    }
    float o0 = lb2[0], o1 = lb2[1];
#pragma unroll
    for (int j = 0; j < 16; j++) {
        float r = fmaxf(hid[j], 0.f);
        o0 += r * lw2[j * 2 + 0];
        o1 += r * lw2[j * 2 + 1];
    }
    out[g * 2 + 0] = o0;
    out[g * 2 + 1] = o1;
}

// ---------------- launcher ----------------
extern "C" void kernel_launch(void* const* d_in, const int* in_sizes, int n_in,
                              void* d_out, int out_size) {
    const float* atom_emb = (const float*)d_in[0];
    const float* W1   = (const float*)d_in[1];
    const float* b1   = (const float*)d_in[2];
    const float* W3   = (const float*)d_in[3];
    const float* b3   = (const float*)d_in[4];
    const float* gam  = (const float*)d_in[5];
    const float* bet  = (const float*)d_in[6];
    const float* lw1  = (const float*)d_in[7];
    const float* lb1  = (const float*)d_in[8];
    const float* lw2  = (const float*)d_in[9];
    const float* lb2  = (const float*)d_in[10];
    const int*   x    = (const int*)d_in[11];
    const int*   ei   = (const int*)d_in[12];
    const int*   batch= (const int*)d_in[13];
    const int* row = ei;
    const int* col = ei + EE;
    float* out = (float*)d_out;

    float *h0, *h1, *t1, *t2, *pool, *cnt, *chstat;
    int *hist;
    __nv_bfloat16 *Bh, *Bl;
    cudaGetSymbolAddress((void**)&h0, g_h0);
    cudaGetSymbolAddress((void**)&h1, g_h1);
    cudaGetSymbolAddress((void**)&t1, g_t1);
    cudaGetSymbolAddress((void**)&t2, g_t2);
    cudaGetSymbolAddress((void**)&hist, g_hist);
    cudaGetSymbolAddress((void**)&pool, g_pool);
    cudaGetSymbolAddress((void**)&cnt, g_cnt);
    cudaGetSymbolAddress((void**)&chstat, g_chstat);
    cudaGetSymbolAddress((void**)&Bh, g_Bh);
    cudaGetSymbolAddress((void**)&Bl, g_Bl);

    const int GEMM_SMEM = 4 * 18432;   // Ah/Al/Bh/Bl, 72 KB
    cudaFuncSetAttribute(k_gemm, cudaFuncAttributeMaxDynamicSharedMemorySize, GEMM_SMEM);

    const int EB = (EE + 255) / 256;
    const int SPMV_B = (NN * 32 + 255) / 256;   // one warp per row
    const int MM_B = (NN + 127) / 128;          // 391 tiles

    // ---- CSR build (histogram -> fused dis+bsum -> fused scan+offsets -> scatter)
    k_zero4<<<(NN / 4 + 255) / 256, 256>>>((float*)hist, NN / 4);
    k_hist<<<EB, 256>>>(row);
    k_disbsum<<<NBLK, 256>>>();
    k_offsets<<<NBLK, 256>>>();
    k_scatter<<<EB, 256>>>(row, col);

    // atom embedding
    k_embed<<<NN, 128>>>(atom_emb, x);

    // conv1: t1 = L h0, t2 = L t1 (raw; Cheb fix-up folded into weights)
    k_prepB<<<128, 384>>>(W1);
    k_spmv<<<SPMV_B, 256>>>(h0, t1);
    k_spmv<<<SPMV_B, 256>>>(t1, t2);
    k_gemm<<<MM_B, 256, GEMM_SMEM>>>(h0, t1, t2, Bh, Bl, b1, h1);

    // conv2 (conv3 weights), writes into h0
    k_prepB<<<128, 384>>>(W3);
    k_spmv<<<SPMV_B, 256>>>(h1, t1);
    k_spmv<<<SPMV_B, 256>>>(t1, t2);
    k_gemm<<<MM_B, 256, GEMM_SMEM>>>(h1, t1, t2, Bh, Bl, b3, h0);

    // BN stats + pooling + counts (fused); BN affine applied post-pool
    k_zero4<<<(GG * CC / 4 + 255) / 256, 256>>>(pool, GG * CC / 4);
    k_zero4<<<1, 128>>>(cnt, GG / 4);
    k_zero4<<<1, 64>>>(chstat, 2 * CC / 4);
    k_statspool<<<(NN + 127) / 128, 128>>>(h0, batch);
    k_bnprep<<<1, 128>>>(gam, bet);

    // head MLP
    k_mlp<<<2, 256>>>(lw1, lb1, lw2, lb2, out);
}

// round 12
// speedup vs baseline: 1.0634x; 1.0634x over previous
#include <cuda_runtime.h>
#include <cuda_bf16.h>
#include <cstdint>

#define NN 50000
#define EE 800000
#define GG 512
#define CC 128
#define NBLK 196          // ceil(NN/256) node tiles
#define CSRB 148          // CSR builder blocks (all co-resident)

// ---------------- scratch (static device arrays; no allocation) ----------------
__device__ float g_h0[NN*CC];
__device__ float g_h1[NN*CC];
__device__ float g_t1[NN*CC];
__device__ float g_t2[NN*CC];
__device__ float g_dis[NN];
__device__ int   g_hist[NN];
__device__ int   g_ptr[NN+1];
__device__ int   g_fill[NN];
__device__ int   g_bsum[NBLK];
__device__ int   g_sync[8];          // grid-barrier counters (self-reset each run)
__device__ int2  g_epk[EE];          // packed CSR: (col, bits(norm))
__device__ float g_pool[GG*CC];
__device__ float g_cnt[GG];
__device__ float g_chsum[CC];
__device__ float g_chsq[CC];
__device__ float g_bna[CC];
__device__ float g_bnb[CC];
// split-bf16 weight matrices, B[n][k] layout (transposed, folded), 128 x 384
__device__ __align__(16) __nv_bfloat16 g_Bh[CC*384];
__device__ __align__(16) __nv_bfloat16 g_Bl[CC*384];

// ---------------- mma.sync helpers (baseline PTX, works at compute_103) --------
__device__ __forceinline__ void ldsm4(uint32_t* r, uint32_t addr) {
    asm volatile("ldmatrix.sync.aligned.m8n8.x4.shared.b16 {%0,%1,%2,%3}, [%4];"
                 : "=r"(r[0]), "=r"(r[1]), "=r"(r[2]), "=r"(r[3]) : "r"(addr));
}
__device__ __forceinline__ void mma16816(float* c, const uint32_t* a, const uint32_t* b) {
    asm volatile("mma.sync.aligned.m16n8k16.row.col.f32.bf16.bf16.f32 "
                 "{%0,%1,%2,%3}, {%4,%5,%6,%7}, {%8,%9}, {%0,%1,%2,%3};"
                 : "+f"(c[0]), "+f"(c[1]), "+f"(c[2]), "+f"(c[3])
                 : "r"(a[0]), "r"(a[1]), "r"(a[2]), "r"(a[3]), "r"(b[0]), "r"(b[1]));
}
__device__ __forceinline__ uint32_t smem_u32(const void* p) {
    uint32_t a;
    asm("{ .reg .u64 t; cvta.to.shared.u64 t, %1; cvt.u32.u64 %0, t; }" : "=r"(a) : "l"(p));
    return a;
}

// ---------------- small utility kernels ----------------
__global__ void k_zero4(float* __restrict__ p, int n4) {
    int i = blockIdx.x * blockDim.x + threadIdx.x;
    if (i < n4) ((float4*)p)[i] = make_float4(0.f, 0.f, 0.f, 0.f);
}

// ---------------- fused CSR build (single grid-resident kernel) ----------------
__device__ __forceinline__ void gridbar(int idx) {
    __syncthreads();
    if (threadIdx.x == 0) {
        __threadfence();
        atomicAdd(&g_sync[idx], 1);
        while (atomicAdd(&g_sync[idx], 0) < CSRB) { }
    }
    __syncthreads();
}

__global__ void __launch_bounds__(256)
k_csr(const int* __restrict__ row, const int* __restrict__ col) {
    __shared__ int sh[256];
    __shared__ int sb[256];
    int tid = threadIdx.x, b = blockIdx.x;
    int gt = b * 256 + tid;
    const int GT = CSRB * 256;

    // P0: zero histogram
    for (int n = gt; n < NN; n += GT) g_hist[n] = 0;
    gridbar(0);

    // P1: degree histogram
    for (int e = gt; e < EE; e += GT) atomicAdd(&g_hist[row[e]], 1);
    gridbar(1);

    // P2: per-node dis + per-tile sums (tiles of 256 nodes)
    for (int t = b; t < NBLK; t += CSRB) {
        int n = t * 256 + tid;
        int h = (n < NN) ? g_hist[n] : 0;
        if (n < NN) g_dis[n] = (h > 0) ? rsqrtf((float)h) : 0.f;
        sh[tid] = h;
        __syncthreads();
        for (int s = 128; s > 0; s >>= 1) {
            if (tid < s) sh[tid] += sh[tid + s];
            __syncthreads();
        }
        if (tid == 0) g_bsum[t] = sh[0];
        __syncthreads();
    }
    gridbar(2);

    // P3: offsets — every block redundantly scans tile sums, then local scans
    int bv = (tid < NBLK) ? g_bsum[tid] : 0;
    sb[tid] = bv;
    __syncthreads();
    for (int o = 1; o < 256; o <<= 1) {
        int x = (tid >= o) ? sb[tid - o] : 0;
        __syncthreads();
        sb[tid] += x;
        __syncthreads();
    }
    for (int t = b; t < NBLK; t += CSRB) {
        int base = (t == 0) ? 0 : sb[t - 1];
        int n = t * 256 + tid;
        int v = (n < NN) ? g_hist[n] : 0;
        sh[tid] = v;
        __syncthreads();
        for (int o = 1; o < 256; o <<= 1) {
            int x = (tid >= o) ? sh[tid - o] : 0;
            __syncthreads();
            sh[tid] += x;
            __syncthreads();
        }
        int off = base + sh[tid] - v;
        if (n < NN) { g_ptr[n] = off; g_fill[n] = off; }
        if (n == NN - 1) g_ptr[NN] = off + v;
        __syncthreads();
    }
    gridbar(3);

    // P4: scatter packed (col, norm) into CSR slots
    for (int e = gt; e < EE; e += GT) {
        int r = row[e], c = col[e];
        int pos = atomicAdd(&g_fill[r], 1);
        float w = -(g_dis[r] * g_dis[c]);
        g_epk[pos] = make_int2(c, __float_as_int(w));
    }

    // exit protocol: block 0 resets barrier counters for graph replay
    __syncthreads();
    if (tid == 0) {
        __threadfence();
        atomicAdd(&g_sync[4], 1);
        if (b == 0) {
            while (atomicAdd(&g_sync[4], 0) < CSRB) { }
            for (int i = 0; i < 8; i++) g_sync[i] = 0;
            __threadfence();
        }
    }
}

// gather-SpMV: dst[r] = sum_j norm_j * src[col_j]   (one warp per row, no atomics)
__global__ void __launch_bounds__(256)
k_spmv(const float* __restrict__ src, float* __restrict__ dst) {
    int w = (blockIdx.x * 256 + threadIdx.x) >> 5;
    if (w >= NN) return;
    int lane = threadIdx.x & 31;
    int s = g_ptr[w], e = g_ptr[w + 1];
    float4 acc = make_float4(0.f, 0.f, 0.f, 0.f);
    for (int j = s; j < e; j += 32) {
        int idx = j + lane;
        int2 pk = (idx < e) ? g_epk[idx] : make_int2(0, 0);
        int cnt = min(32, e - j);
        for (int k = 0; k < cnt; k++) {
            int ck = __shfl_sync(0xffffffffu, pk.x, k);
            float wk = __uint_as_float(__shfl_sync(0xffffffffu, (unsigned)pk.y, k));
            float4 v = ((const float4*)(src + (size_t)ck * CC))[lane];
            acc.x = fmaf(wk, v.x, acc.x);
            acc.y = fmaf(wk, v.y, acc.y);
            acc.z = fmaf(wk, v.z, acc.z);
            acc.w = fmaf(wk, v.w, acc.w);
        }
    }
    ((float4*)(dst + (size_t)w * CC))[lane] = acc;
}

// AtomEncoder: h0[n,c] = sum_f atom_emb[f, x[n,f], c]
__global__ void k_embed(const float* __restrict__ emb, const int* __restrict__ x) {
    int n = blockIdx.x;
    __shared__ int xs[9];
    if (threadIdx.x < 9) xs[threadIdx.x] = x[n * 9 + threadIdx.x];
    __syncthreads();
    int c = threadIdx.x;
    float s = 0.f;
#pragma unroll
    for (int f = 0; f < 9; f++)
        s += emb[((f * 119) + xs[f]) * CC + c];
    g_h0[(size_t)n * CC + c] = s;
}

// Build folded, transposed, split-bf16 weights:
//   Bmod[k][n]: k in [0,128)   -> W0[k][n] - W2[k][n]
//               k in [128,256) -> W1[k-128][n]
//               k in [256,384) -> 2*W2[k-256][n]
__global__ void k_prepB(const float* __restrict__ W) {
    int n = blockIdx.x;       // 0..127
    int k = threadIdx.x;      // 0..383
    int blk = k >> 7, ci = k & 127;
    float w;
    if (blk == 0)      w = W[ci * 128 + n] - W[2 * 16384 + ci * 128 + n];
    else if (blk == 1) w = W[16384 + ci * 128 + n];
    else               w = 2.f * W[2 * 16384 + ci * 128 + n];
    __nv_bfloat16 hi = __float2bfloat16(w);
    g_Bh[n * 384 + k] = hi;
    g_Bl[n * 384 + k] = __float2bfloat16(w - __bfloat162float(hi));
}

// mma.sync split-bf16 GEMM: out = relu([A0|A1|A2] @ Bmod^T + bias)
// Block: 128x128 tile. 8 warps (4 M x 2 N), warp tile 32x64.
#define ASTR 144   // smem row stride in bytes (72 bf16, conflict-free for ldmatrix)
__global__ void __launch_bounds__(256)
k_gemm(const float* __restrict__ A0, const float* __restrict__ A1,
       const float* __restrict__ A2, const __nv_bfloat16* __restrict__ Bh_,
       const __nv_bfloat16* __restrict__ Bl_, const float* __restrict__ bias,
       float* __restrict__ out)
{
    extern __shared__ char sm[];
    char* pAH = sm;
    char* pAL = sm + 18432;
    char* pBH = sm + 36864;
    char* pBL = sm + 55296;
    uint32_t sb = smem_u32(sm);
    uint32_t aAH = sb, aAL = sb + 18432, aBH = sb + 36864, aBL = sb + 55296;

    int tid = threadIdx.x;
    int lane = tid & 31, wid = tid >> 5;
    int wm = (wid & 3) * 32;
    int wn = (wid >> 2) * 64;
    int m0 = blockIdx.x * 128;

    float acc[2][8][4];
#pragma unroll
    for (int mi = 0; mi < 2; mi++)
#pragma unroll
        for (int nj = 0; nj < 8; nj++)
#pragma unroll
            for (int q = 0; q < 4; q++) acc[mi][nj][q] = 0.f;

    const float* srcs[3] = {A0, A1, A2};
    const uint2* BhG = (const uint2*)Bh_;
    const uint2* BlG = (const uint2*)Bl_;

    for (int ch = 0; ch < 6; ch++) {
        const float4* S4 = (const float4*)srcs[ch >> 1];
        int k4off = (ch & 1) * 16;
#pragma unroll
        for (int it = 0; it < 8; it++) {
            int idx = it * 256 + tid;
            int r = idx >> 4, kq = idx & 15;
            int rg = m0 + r;
            float4 v = (rg < NN) ? S4[(size_t)rg * 32 + k4off + kq]
                                 : make_float4(0.f, 0.f, 0.f, 0.f);
            __nv_bfloat162 h01 = __floats2bfloat162_rn(v.x, v.y);
            __nv_bfloat162 h23 = __floats2bfloat162_rn(v.z, v.w);
            __nv_bfloat162 l01 = __floats2bfloat162_rn(v.x - __bfloat162float(h01.x),
                                                       v.y - __bfloat162float(h01.y));
            __nv_bfloat162 l23 = __floats2bfloat162_rn(v.z - __bfloat162float(h23.x),
                                                       v.w - __bfloat162float(h23.y));
            int off = r * ASTR + kq * 8;
            *(__nv_bfloat162*)(pAH + off)     = h01;
            *(__nv_bfloat162*)(pAH + off + 4) = h23;
            *(__nv_bfloat162*)(pAL + off)     = l01;
            *(__nv_bfloat162*)(pAL + off + 4) = l23;
        }
        int kbG = ch * 16;
#pragma unroll
        for (int it = 0; it < 8; it++) {
            int idx = it * 256 + tid;
            int n = idx >> 4, kq = idx & 15;
            int off = n * ASTR + kq * 8;
            *(uint2*)(pBH + off) = BhG[n * 96 + kbG + kq];
            *(uint2*)(pBL + off) = BlG[n * 96 + kbG + kq];
        }
        __syncthreads();

#pragma unroll
        for (int ks = 0; ks < 4; ks++) {
            int kb = ks * 16;
            uint32_t ah[2][4], al[2][4], bh[8][2], bl[8][2];
            uint32_t aoff = (uint32_t)((wm + (lane & 15)) * ASTR
                          + (kb + ((lane >> 4) << 3)) * 2);
            ldsm4(ah[0], aAH + aoff);
            ldsm4(ah[1], aAH + aoff + 16 * ASTR);
            ldsm4(al[0], aAL + aoff);
            ldsm4(al[1], aAL + aoff + 16 * ASTR);
            uint32_t boff = (uint32_t)((wn + ((lane >> 4) << 3) + (lane & 7)) * ASTR
                          + (kb + (((lane >> 3) & 1) << 3)) * 2);
#pragma unroll
            for (int p = 0; p < 4; p++) {
                uint32_t r4[4];
                ldsm4(r4, aBH + boff + p * 16 * ASTR);
                bh[2*p][0] = r4[0]; bh[2*p][1] = r4[1];
                bh[2*p+1][0] = r4[2]; bh[2*p+1][1] = r4[3];
                ldsm4(r4, aBL + boff + p * 16 * ASTR);
                bl[2*p][0] = r4[0]; bl[2*p][1] = r4[1];
                bl[2*p+1][0] = r4[2]; bl[2*p+1][1] = r4[3];
            }
#pragma unroll
            for (int mi = 0; mi < 2; mi++)
#pragma unroll
                for (int nj = 0; nj < 8; nj++) {
                    mma16816(acc[mi][nj], ah[mi], bh[nj]);
                    mma16816(acc[mi][nj], ah[mi], bl[nj]);
                    mma16816(acc[mi][nj], al[mi], bh[nj]);
                }
        }
        __syncthreads();
    }

#pragma unroll
    for (int mi = 0; mi < 2; mi++) {
        int r0 = m0 + wm + mi * 16 + (lane >> 2);
#pragma unroll
        for (int nj = 0; nj < 8; nj++) {
            int c = wn + nj * 8 + 2 * (lane & 3);
            float bx = __ldg(bias + c), by = __ldg(bias + c + 1);
            if (r0 < NN) {
                float2 o;
                o.x = fmaxf(acc[mi][nj][0] + bx, 0.f);
                o.y = fmaxf(acc[mi][nj][1] + by, 0.f);
                *(float2*)(out + (size_t)r0 * CC + c) = o;
            }
            if (r0 + 8 < NN) {
                float2 o;
                o.x = fmaxf(acc[mi][nj][2] + bx, 0.f);
                o.y = fmaxf(acc[mi][nj][3] + by, 0.f);
                *(float2*)(out + (size_t)(r0 + 8) * CC + c) = o;
            }
        }
    }
}

// per-graph node counts
__global__ void k_cnt(const int* __restrict__ batch) {
    int n = blockIdx.x * blockDim.x + threadIdx.x;
    if (n < NN) atomicAdd(&g_cnt[batch[n]], 1.0f);
}

// channel sums/sumsq (for BN) + per-graph pooling sums (batch sorted -> run accumulation)
__global__ void k_statspool(const float* __restrict__ h, const int* __restrict__ batch) {
    int c = threadIdx.x;
    int base = blockIdx.x * 128;
    float s = 0.f, sq = 0.f, acc = 0.f;
    int cur = -1;
    for (int r = 0; r < 128; r++) {
        int n = base + r;
        if (n >= NN) break;
        int g = batch[n];
        float v = h[(size_t)n * CC + c];
        s += v;
        sq += v * v;
        if (g != cur) {
            if (cur >= 0) atomicAdd(&g_pool[cur * CC + c], acc);
            cur = g;
            acc = 0.f;
        }
        acc += v;
    }
    if (cur >= 0) atomicAdd(&g_pool[cur * CC + c], acc);
    atomicAdd(&g_chsum[c], s);
    atomicAdd(&g_chsq[c], sq);
}

__global__ void k_bnprep(const float* __restrict__ gamma, const float* __restrict__ beta) {
    int c = threadIdx.x;
    float mu = g_chsum[c] * (1.0f / NN);
    float var = fmaxf(g_chsq[c] * (1.0f / NN) - mu * mu, 0.f);
    float inv = rsqrtf(var + 1e-5f);
    float a = gamma[c] * inv;
    g_bna[c] = a;
    g_bnb[c] = beta[c] - mu * a;
}

__global__ void k_mlp(const float* __restrict__ lw1, const float* __restrict__ lb1,
                      const float* __restrict__ lw2, const float* __restrict__ lb2,
                      float* __restrict__ out) {
    int g = blockIdx.x * blockDim.x + threadIdx.x;
    if (g >= GG) return;
    float inv = 1.0f / fmaxf(g_cnt[g], 1.0f);
    float hid[16];
#pragma unroll
    for (int j = 0; j < 16; j++) hid[j] = lb1[j];
#pragma unroll 4
    for (int c = 0; c < CC; c++) {
        float pb = g_pool[g * CC + c] * inv * g_bna[c] + g_bnb[c];
        const float4* w4 = (const float4*)(lw1 + c * 16);
#pragma unroll
        for (int q = 0; q < 4; q++) {
            float4 w = w4[q];
            hid[q * 4 + 0] += pb * w.x;
            hid[q * 4 + 1] += pb * w.y;
            hid[q * 4 + 2] += pb * w.z;
            hid[q * 4 + 3] += pb * w.w;
        }
    }
    float o0 = lb2[0], o1 = lb2[1];
#pragma unroll
    for (int j = 0; j < 16; j++) {
        float r = fmaxf(hid[j], 0.f);
        o0 += r * lw2[j * 2 + 0];
        o1 += r * lw2[j * 2 + 1];
    }
    out[g * 2 + 0] = o0;
    out[g * 2 + 1] = o1;
}

// ---------------- launcher ----------------
extern "C" void kernel_launch(void* const* d_in, const int* in_sizes, int n_in,
                              void* d_out, int out_size) {
    const float* atom_emb = (const float*)d_in[0];
    const float* W1   = (const float*)d_in[1];
    const float* b1   = (const float*)d_in[2];
    const float* W3   = (const float*)d_in[3];
    const float* b3   = (const float*)d_in[4];
    const float* gam  = (const float*)d_in[5];
    const float* bet  = (const float*)d_in[6];
    const float* lw1  = (const float*)d_in[7];
    const float* lb1  = (const float*)d_in[8];
    const float* lw2  = (const float*)d_in[9];
    const float* lb2  = (const float*)d_in[10];
    const int*   x    = (const int*)d_in[11];
    const int*   ei   = (const int*)d_in[12];
    const int*   batch= (const int*)d_in[13];
    const int* row = ei;
    const int* col = ei + EE;
    float* out = (float*)d_out;

    float *h0, *h1, *t1, *t2, *pool, *cnt, *chsum, *chsq;
    __nv_bfloat16 *Bh, *Bl;
    cudaGetSymbolAddress((void**)&h0, g_h0);
    cudaGetSymbolAddress((void**)&h1, g_h1);
    cudaGetSymbolAddress((void**)&t1, g_t1);
    cudaGetSymbolAddress((void**)&t2, g_t2);
    cudaGetSymbolAddress((void**)&pool, g_pool);
    cudaGetSymbolAddress((void**)&cnt, g_cnt);
    cudaGetSymbolAddress((void**)&chsum, g_chsum);
    cudaGetSymbolAddress((void**)&chsq, g_chsq);
    cudaGetSymbolAddress((void**)&Bh, g_Bh);
    cudaGetSymbolAddress((void**)&Bl, g_Bl);

    const int GEMM_SMEM = 4 * 18432;   // Ah/Al/Bh/Bl, 72 KB
    cudaFuncSetAttribute(k_gemm, cudaFuncAttributeMaxDynamicSharedMemorySize, GEMM_SMEM);

    const int NB = (NN + 255) / 256;
    const int SPMV_B = (NN * 32 + 255) / 256;   // one warp per row
    const int MM_B = (NN + 127) / 128;          // 391 tiles

    // (1) fused CSR build: zero -> hist -> dis/tilesum -> scan/offsets -> scatter
    k_csr<<<CSRB, 256>>>(row, col);
    // (2) atom embedding
    k_embed<<<NN, 128>>>(atom_emb, x);
    // (3) fold conv1 weights
    k_prepB<<<128, 384>>>(W1);

    // conv1: t1 = L h0 (4th launch -> ncu-profiled), t2 = L t1
    k_spmv<<<SPMV_B, 256>>>(h0, t1);
    k_spmv<<<SPMV_B, 256>>>(t1, t2);
    k_gemm<<<MM_B, 256, GEMM_SMEM>>>(h0, t1, t2, Bh, Bl, b1, h1);

    // conv2 (conv3 weights), writes into h0
    k_prepB<<<128, 384>>>(W3);
    k_spmv<<<SPMV_B, 256>>>(h1, t1);
    k_spmv<<<SPMV_B, 256>>>(t1, t2);
    k_gemm<<<MM_B, 256, GEMM_SMEM>>>(h1, t1, t2, Bh, Bl, b3, h0);

    // BN stats + pooling (R7-proven tail); BN affine applied post-pool
    k_zero4<<<(GG * CC / 4 + 255) / 256, 256>>>(pool, GG * CC / 4);
    k_zero4<<<1, 128>>>(cnt, GG / 4);
    k_zero4<<<1, 32>>>(chsum, CC / 4);
    k_zero4<<<1, 32>>>(chsq, CC / 4);
    k_cnt<<<NB, 256>>>(batch);
    k_statspool<<<(NN + 127) / 128, 128>>>(h0, batch);
    k_bnprep<<<1, 128>>>(gam, bet);

    // head MLP
    k_mlp<<<2, 256>>>(lw1, lb1, lw2, lb2, out);
}

// round 13
// speedup vs baseline: 1.3683x; 1.2868x over previous
#include <cuda_runtime.h>
#include <cuda_bf16.h>
#include <cstdint>

#define NN 50000
#define EE 800000
#define GG 512
#define CC 128
#define NBLK 196          // ceil(NN/256) node tiles
#define CSRB 148          // CSR builder blocks (all co-resident)

// ---------------- scratch (static device arrays; no allocation) ----------------
__device__ float g_h0[NN*CC];
__device__ float g_h1[NN*CC];
__device__ float g_t1[NN*CC];
__device__ float g_t2[NN*CC];
__device__ float g_dis[NN];
__device__ int   g_hist[NN];
__device__ int   g_ptr[NN+1];
__device__ int   g_fill[NN];
__device__ int   g_bsum[NBLK];
__device__ int   g_sync[8];          // grid-barrier counters (self-reset each run)
__device__ int2  g_epk[EE];          // packed CSR: (col, bits(norm))
__device__ float g_pool[GG*CC];
__device__ float g_cnt[GG];
__device__ float g_chsum[CC];
__device__ float g_chsq[CC];
__device__ float g_bna[CC];
__device__ float g_bnb[CC];
// split-bf16 weights for BOTH convs: [conv][n*384+k] (transposed, folded)
__device__ __align__(16) __nv_bfloat16 g_Bh[2][CC*384];
__device__ __align__(16) __nv_bfloat16 g_Bl[2][CC*384];

// ---------------- mma.sync helpers (baseline PTX, works at compute_103) --------
__device__ __forceinline__ void ldsm4(uint32_t* r, uint32_t addr) {
    asm volatile("ldmatrix.sync.aligned.m8n8.x4.shared.b16 {%0,%1,%2,%3}, [%4];"
                 : "=r"(r[0]), "=r"(r[1]), "=r"(r[2]), "=r"(r[3]) : "r"(addr));
}
__device__ __forceinline__ void mma16816(float* c, const uint32_t* a, const uint32_t* b) {
    asm volatile("mma.sync.aligned.m16n8k16.row.col.f32.bf16.bf16.f32 "
                 "{%0,%1,%2,%3}, {%4,%5,%6,%7}, {%8,%9}, {%0,%1,%2,%3};"
                 : "+f"(c[0]), "+f"(c[1]), "+f"(c[2]), "+f"(c[3])
                 : "r"(a[0]), "r"(a[1]), "r"(a[2]), "r"(a[3]), "r"(b[0]), "r"(b[1]));
}
__device__ __forceinline__ uint32_t smem_u32(const void* p) {
    uint32_t a;
    asm("{ .reg .u64 t; cvta.to.shared.u64 t, %1; cvt.u32.u64 %0, t; }" : "=r"(a) : "l"(p));
    return a;
}
#define CP_ASYNC16(dst, src) \
    asm volatile("cp.async.cg.shared.global [%0], [%1], 16;" \
                 :: "r"(dst), "l"(src) : "memory")
#define CP_COMMIT() asm volatile("cp.async.commit_group;" ::: "memory")
#define CP_WAIT0()  asm volatile("cp.async.wait_group 0;" ::: "memory")

// ---------------- small utility kernels ----------------
__global__ void k_zero4(float* __restrict__ p, int n4) {
    int i = blockIdx.x * blockDim.x + threadIdx.x;
    if (i < n4) ((float4*)p)[i] = make_float4(0.f, 0.f, 0.f, 0.f);
}

// ---------------- fused CSR build (single grid-resident kernel) ----------------
__device__ __forceinline__ void gridbar(int idx) {
    __syncthreads();
    if (threadIdx.x == 0) {
        __threadfence();
        atomicAdd(&g_sync[idx], 1);
        while (atomicAdd(&g_sync[idx], 0) < CSRB) { }
    }
    __syncthreads();
}

__global__ void __launch_bounds__(256)
k_csr(const int* __restrict__ row, const int* __restrict__ col) {
    __shared__ int sh[256];
    __shared__ int sb[256];
    int tid = threadIdx.x, b = blockIdx.x;
    int gt = b * 256 + tid;
    const int GT = CSRB * 256;

    for (int n = gt; n < NN; n += GT) g_hist[n] = 0;
    gridbar(0);

    for (int e = gt; e < EE; e += GT) atomicAdd(&g_hist[row[e]], 1);
    gridbar(1);

    for (int t = b; t < NBLK; t += CSRB) {
        int n = t * 256 + tid;
        int h = (n < NN) ? g_hist[n] : 0;
        if (n < NN) g_dis[n] = (h > 0) ? rsqrtf((float)h) : 0.f;
        sh[tid] = h;
        __syncthreads();
        for (int s = 128; s > 0; s >>= 1) {
            if (tid < s) sh[tid] += sh[tid + s];
            __syncthreads();
        }
        if (tid == 0) g_bsum[t] = sh[0];
        __syncthreads();
    }
    gridbar(2);

    int bv = (tid < NBLK) ? g_bsum[tid] : 0;
    sb[tid] = bv;
    __syncthreads();
    for (int o = 1; o < 256; o <<= 1) {
        int x = (tid >= o) ? sb[tid - o] : 0;
        __syncthreads();
        sb[tid] += x;
        __syncthreads();
    }
    for (int t = b; t < NBLK; t += CSRB) {
        int base = (t == 0) ? 0 : sb[t - 1];
        int n = t * 256 + tid;
        int v = (n < NN) ? g_hist[n] : 0;
        sh[tid] = v;
        __syncthreads();
        for (int o = 1; o < 256; o <<= 1) {
            int x = (tid >= o) ? sh[tid - o] : 0;
            __syncthreads();
            sh[tid] += x;
            __syncthreads();
        }
        int off = base + sh[tid] - v;
        if (n < NN) { g_ptr[n] = off; g_fill[n] = off; }
        if (n == NN - 1) g_ptr[NN] = off + v;
        __syncthreads();
    }
    gridbar(3);

    for (int e = gt; e < EE; e += GT) {
        int r = row[e], c = col[e];
        int pos = atomicAdd(&g_fill[r], 1);
        float w = -(g_dis[r] * g_dis[c]);
        g_epk[pos] = make_int2(c, __float_as_int(w));
    }

    __syncthreads();
    if (tid == 0) {
        __threadfence();
        atomicAdd(&g_sync[4], 1);
        if (b == 0) {
            while (atomicAdd(&g_sync[4], 0) < CSRB) { }
            for (int i = 0; i < 8; i++) g_sync[i] = 0;
            __threadfence();
        }
    }
}

// gather-SpMV: dst[r] = sum_j norm_j * src[col_j]   (one warp per row, no atomics)
// at the LTS cap (~11.4 TB/s); do not touch
__global__ void __launch_bounds__(256)
k_spmv(const float* __restrict__ src, float* __restrict__ dst) {
    int w = (blockIdx.x * 256 + threadIdx.x) >> 5;
    if (w >= NN) return;
    int lane = threadIdx.x & 31;
    int s = g_ptr[w], e = g_ptr[w + 1];
    float4 acc = make_float4(0.f, 0.f, 0.f, 0.f);
    for (int j = s; j < e; j += 32) {
        int idx = j + lane;
        int2 pk = (idx < e) ? g_epk[idx] : make_int2(0, 0);
        int cnt = min(32, e - j);
        for (int k = 0; k < cnt; k++) {
            int ck = __shfl_sync(0xffffffffu, pk.x, k);
            float wk = __uint_as_float(__shfl_sync(0xffffffffu, (unsigned)pk.y, k));
            float4 v = ((const float4*)(src + (size_t)ck * CC))[lane];
            acc.x = fmaf(wk, v.x, acc.x);
            acc.y = fmaf(wk, v.y, acc.y);
            acc.z = fmaf(wk, v.z, acc.z);
            acc.w = fmaf(wk, v.w, acc.w);
        }
    }
    ((float4*)(dst + (size_t)w * CC))[lane] = acc;
}

// AtomEncoder: h0[n,c] = sum_f atom_emb[f, x[n,f], c]
__global__ void k_embed(const float* __restrict__ emb, const int* __restrict__ x) {
    int n = blockIdx.x;
    __shared__ int xs[9];
    if (threadIdx.x < 9) xs[threadIdx.x] = x[n * 9 + threadIdx.x];
    __syncthreads();
    int c = threadIdx.x;
    float s = 0.f;
#pragma unroll
    for (int f = 0; f < 9; f++)
        s += emb[((f * 119) + xs[f]) * CC + c];
    g_h0[(size_t)n * CC + c] = s;
}

// Build folded, transposed, split-bf16 weights for BOTH convs in one launch.
//   Bmod[k][n]: k in [0,128)->W0-W2 ; [128,256)->W1 ; [256,384)->2*W2
__global__ void k_prepB2(const float* __restrict__ WA, const float* __restrict__ WB) {
    int which = blockIdx.x >> 7;
    int n = blockIdx.x & 127;
    int k = threadIdx.x;      // 0..383
    const float* W = which ? WB : WA;
    int blk = k >> 7, ci = k & 127;
    float w;
    if (blk == 0)      w = W[ci * 128 + n] - W[2 * 16384 + ci * 128 + n];
    else if (blk == 1) w = W[16384 + ci * 128 + n];
    else               w = 2.f * W[2 * 16384 + ci * 128 + n];
    __nv_bfloat16 hi = __float2bfloat16(w);
    g_Bh[which][n * 384 + k] = hi;
    g_Bl[which][n * 384 + k] = __float2bfloat16(w - __bfloat162float(hi));
}

// double-buffered mma.sync split-bf16 GEMM: out = relu([A0|A1|A2] @ Bmod^T + bias)
// Block 128x128 tile, 8 warps (4Mx2N). K=384 in 12 chunks of 32, 2 smem stages,
// 1 sync/chunk. A prefetched to regs (LDG) + converted after MMAs; B via cp.async.
#define BSTR 80                     // bytes per smem plane row (64 data + 16 pad)
#define PLANE (128 * BSTR)          // 10240 B
#define STAGE (4 * PLANE)           // Ah|Al|Bh|Bl = 40960 B
__global__ void __launch_bounds__(256, 2)
k_gemm(const float* __restrict__ A0, const float* __restrict__ A1,
       const float* __restrict__ A2, const __nv_bfloat16* __restrict__ Bh_,
       const __nv_bfloat16* __restrict__ Bl_, const float* __restrict__ bias,
       float* __restrict__ out)
{
    extern __shared__ char sm[];
    uint32_t sb = smem_u32(sm);
    char* smc = sm;

    int tid = threadIdx.x;
    int lane = tid & 31, wid = tid >> 5;
    int wm = (wid & 3) * 32;
    int wn = (wid >> 2) * 64;
    int m0 = blockIdx.x * 128;

    float acc[2][8][4];
#pragma unroll
    for (int mi = 0; mi < 2; mi++)
#pragma unroll
        for (int nj = 0; nj < 8; nj++)
#pragma unroll
            for (int q = 0; q < 4; q++) acc[mi][nj][q] = 0.f;

    const float* srcs[3] = {A0, A1, A2};
    const char* BhC = (const char*)Bh_;
    const char* BlC = (const char*)Bl_;

    // per-thread A-load geometry: 4 float4 (rows rb, rb+32, rb+64, rb+96; q const)
    int rb = tid >> 3;          // 0..31
    int q  = tid & 7;           // float4 index within 32-float row-chunk
    // per-thread B cp.async geometry: 2 segs/plane (seg = tid, tid+256)
    int n0 = tid >> 2,  p0 = tid & 3;
    int n1 = (tid + 256) >> 2, p1 = (tid + 256) & 3;

    float4 pa[4];

    // ---- prologue: chunk 0
    {
        const float4* S4 = (const float4*)srcs[0];
#pragma unroll
        for (int i = 0; i < 4; i++) {
            int rg = m0 + rb + 32 * i;
            pa[i] = (rg < NN) ? S4[(size_t)rg * 32 + q] : make_float4(0.f, 0.f, 0.f, 0.f);
        }
        uint32_t dBH = sb + 2 * PLANE, dBL = sb + 3 * PLANE;
        CP_ASYNC16(dBH + n0 * BSTR + p0 * 16, BhC + n0 * 768 + p0 * 16);
        CP_ASYNC16(dBH + n1 * BSTR + p1 * 16, BhC + n1 * 768 + p1 * 16);
        CP_ASYNC16(dBL + n0 * BSTR + p0 * 16, BlC + n0 * 768 + p0 * 16);
        CP_ASYNC16(dBL + n1 * BSTR + p1 * 16, BlC + n1 * 768 + p1 * 16);
        CP_COMMIT();
#pragma unroll
        for (int i = 0; i < 4; i++) {
            float4 v = pa[i];
            __nv_bfloat162 h01 = __floats2bfloat162_rn(v.x, v.y);
            __nv_bfloat162 h23 = __floats2bfloat162_rn(v.z, v.w);
            __nv_bfloat162 l01 = __floats2bfloat162_rn(v.x - __bfloat162float(h01.x),
                                                       v.y - __bfloat162float(h01.y));
            __nv_bfloat162 l23 = __floats2bfloat162_rn(v.z - __bfloat162float(h23.x),
                                                       v.w - __bfloat162float(h23.y));
            int off = (rb + 32 * i) * BSTR + q * 8;
            *(__nv_bfloat162*)(smc + off)         = h01;
            *(__nv_bfloat162*)(smc + off + 4)     = h23;
            *(__nv_bfloat162*)(smc + PLANE + off)     = l01;
            *(__nv_bfloat162*)(smc + PLANE + off + 4) = l23;
        }
        CP_WAIT0();
        __syncthreads();
    }

    for (int ch = 0; ch < 12; ch++) {
        int s = ch & 1;
        int have_next = (ch + 1 < 12);
        // ---- prefetch chunk ch+1: A -> regs, B -> cp.async into stage 1-s
        if (have_next) {
            int nc = ch + 1;
            const float4* S4 = (const float4*)srcs[nc >> 2];
            int k4off = (nc & 3) * 8;
#pragma unroll
            for (int i = 0; i < 4; i++) {
                int rg = m0 + rb + 32 * i;
                pa[i] = (rg < NN) ? S4[(size_t)rg * 32 + k4off + q]
                                  : make_float4(0.f, 0.f, 0.f, 0.f);
            }
            uint32_t st = sb + (1 - s) * STAGE;
            uint32_t dBH = st + 2 * PLANE, dBL = st + 3 * PLANE;
            int gk = nc * 64;   // byte offset within 768-byte B row
            CP_ASYNC16(dBH + n0 * BSTR + p0 * 16, BhC + n0 * 768 + gk + p0 * 16);
            CP_ASYNC16(dBH + n1 * BSTR + p1 * 16, BhC + n1 * 768 + gk + p1 * 16);
            CP_ASYNC16(dBL + n0 * BSTR + p0 * 16, BlC + n0 * 768 + gk + p0 * 16);
            CP_ASYNC16(dBL + n1 * BSTR + p1 * 16, BlC + n1 * 768 + gk + p1 * 16);
            CP_COMMIT();
        }

        // ---- MMAs on stage s
        uint32_t st = sb + s * STAGE;
        uint32_t aAH = st, aAL = st + PLANE, aBH = st + 2 * PLANE, aBL = st + 3 * PLANE;
#pragma unroll
        for (int ks = 0; ks < 2; ks++) {
            uint32_t ah[2][4], al[2][4], bh[8][2], bl[8][2];
            uint32_t aoff = (uint32_t)((wm + (lane & 15)) * BSTR
                          + ks * 32 + (lane >> 4) * 16);
            ldsm4(ah[0], aAH + aoff);
            ldsm4(ah[1], aAH + aoff + 16 * BSTR);
            ldsm4(al[0], aAL + aoff);
            ldsm4(al[1], aAL + aoff + 16 * BSTR);
            uint32_t boff = (uint32_t)((wn + ((lane >> 4) << 3) + (lane & 7)) * BSTR
                          + ks * 32 + ((lane >> 3) & 1) * 16);
#pragma unroll
            for (int p = 0; p < 4; p++) {
                uint32_t r4[4];
                ldsm4(r4, aBH + boff + p * 16 * BSTR);
                bh[2*p][0] = r4[0]; bh[2*p][1] = r4[1];
                bh[2*p+1][0] = r4[2]; bh[2*p+1][1] = r4[3];
                ldsm4(r4, aBL + boff + p * 16 * BSTR);
                bl[2*p][0] = r4[0]; bl[2*p][1] = r4[1];
                bl[2*p+1][0] = r4[2]; bl[2*p+1][1] = r4[3];
            }
#pragma unroll
            for (int mi = 0; mi < 2; mi++)
#pragma unroll
                for (int nj = 0; nj < 8; nj++) {
                    mma16816(acc[mi][nj], ah[mi], bh[nj]);
                    mma16816(acc[mi][nj], ah[mi], bl[nj]);
                    mma16816(acc[mi][nj], al[mi], bh[nj]);
                }
        }

        // ---- store prefetched A into stage 1-s, drain B, one sync
        if (have_next) {
            char* stc = smc + (1 - s) * STAGE;
#pragma unroll
            for (int i = 0; i < 4; i++) {
                float4 v = pa[i];
                __nv_bfloat162 h01 = __floats2bfloat162_rn(v.x, v.y);
                __nv_bfloat162 h23 = __floats2bfloat162_rn(v.z, v.w);
                __nv_bfloat162 l01 = __floats2bfloat162_rn(v.x - __bfloat162float(h01.x),
                                                           v.y - __bfloat162float(h01.y));
                __nv_bfloat162 l23 = __floats2bfloat162_rn(v.z - __bfloat162float(h23.x),
                                                           v.w - __bfloat162float(h23.y));
                int off = (rb + 32 * i) * BSTR + q * 8;
                *(__nv_bfloat162*)(stc + off)             = h01;
                *(__nv_bfloat162*)(stc + off + 4)         = h23;
                *(__nv_bfloat162*)(stc + PLANE + off)     = l01;
                *(__nv_bfloat162*)(stc + PLANE + off + 4) = l23;
            }
            CP_WAIT0();
            __syncthreads();
        }
    }

    // ---- epilogue: bias + relu, float2 stores
#pragma unroll
    for (int mi = 0; mi < 2; mi++) {
        int r0 = m0 + wm + mi * 16 + (lane >> 2);
#pragma unroll
        for (int nj = 0; nj < 8; nj++) {
            int c = wn + nj * 8 + 2 * (lane & 3);
            float bx = __ldg(bias + c), by = __ldg(bias + c + 1);
            if (r0 < NN) {
                float2 o;
                o.x = fmaxf(acc[mi][nj][0] + bx, 0.f);
                o.y = fmaxf(acc[mi][nj][1] + by, 0.f);
                *(float2*)(out + (size_t)r0 * CC + c) = o;
            }
            if (r0 + 8 < NN) {
                float2 o;
                o.x = fmaxf(acc[mi][nj][2] + bx, 0.f);
                o.y = fmaxf(acc[mi][nj][3] + by, 0.f);
                *(float2*)(out + (size_t)(r0 + 8) * CC + c) = o;
            }
        }
    }
}

// per-graph node counts
__global__ void k_cnt(const int* __restrict__ batch) {
    int n = blockIdx.x * blockDim.x + threadIdx.x;
    if (n < NN) atomicAdd(&g_cnt[batch[n]], 1.0f);
}

// channel sums/sumsq (for BN) + per-graph pooling sums (batch sorted -> run accumulation)
__global__ void k_statspool(const float* __restrict__ h, const int* __restrict__ batch) {
    int c = threadIdx.x;
    int base = blockIdx.x * 128;
    float s = 0.f, sq = 0.f, acc = 0.f;
    int cur = -1;
    for (int r = 0; r < 128; r++) {
        int n = base + r;
        if (n >= NN) break;
        int g = batch[n];
        float v = h[(size_t)n * CC + c];
        s += v;
        sq += v * v;
        if (g != cur) {
            if (cur >= 0) atomicAdd(&g_pool[cur * CC + c], acc);
            cur = g;
            acc = 0.f;
        }
        acc += v;
    }
    if (cur >= 0) atomicAdd(&g_pool[cur * CC + c], acc);
    atomicAdd(&g_chsum[c], s);
    atomicAdd(&g_chsq[c], sq);
}

__global__ void k_bnprep(const float* __restrict__ gamma, const float* __restrict__ beta) {
    int c = threadIdx.x;
    float mu = g_chsum[c] * (1.0f / NN);
    float var = fmaxf(g_chsq[c] * (1.0f / NN) - mu * mu, 0.f);
    float inv = rsqrtf(var + 1e-5f);
    float a = gamma[c] * inv;
    g_bna[c] = a;
    g_bnb[c] = beta[c] - mu * a;
}

__global__ void k_mlp(const float* __restrict__ lw1, const float* __restrict__ lb1,
                      const float* __restrict__ lw2, const float* __restrict__ lb2,
                      float* __restrict__ out) {
    int g = blockIdx.x * blockDim.x + threadIdx.x;
    if (g >= GG) return;
    float inv = 1.0f / fmaxf(g_cnt[g], 1.0f);
    float hid[16];
#pragma unroll
    for (int j = 0; j < 16; j++) hid[j] = lb1[j];
#pragma unroll 4
    for (int c = 0; c < CC; c++) {
        float pb = g_pool[g * CC + c] * inv * g_bna[c] + g_bnb[c];
        const float4* w4 = (const float4*)(lw1 + c * 16);
#pragma unroll
        for (int qq = 0; qq < 4; qq++) {
            float4 w = w4[qq];
            hid[qq * 4 + 0] += pb * w.x;
            hid[qq * 4 + 1] += pb * w.y;
            hid[qq * 4 + 2] += pb * w.z;
            hid[qq * 4 + 3] += pb * w.w;
        }
    }
    float o0 = lb2[0], o1 = lb2[1];
#pragma unroll
    for (int j = 0; j < 16; j++) {
        float r = fmaxf(hid[j], 0.f);
        o0 += r * lw2[j * 2 + 0];
        o1 += r * lw2[j * 2 + 1];
    }
    out[g * 2 + 0] = o0;
    out[g * 2 + 1] = o1;
}

// ---------------- launcher ----------------
extern "C" void kernel_launch(void* const* d_in, const int* in_sizes, int n_in,
                              void* d_out, int out_size) {
    const float* atom_emb = (const float*)d_in[0];
    const float* W1   = (const float*)d_in[1];
    const float* b1   = (const float*)d_in[2];
    const float* W3   = (const float*)d_in[3];
    const float* b3   = (const float*)d_in[4];
    const float* gam  = (const float*)d_in[5];
    const float* bet  = (const float*)d_in[6];
    const float* lw1  = (const float*)d_in[7];
    const float* lb1  = (const float*)d_in[8];
    const float* lw2  = (const float*)d_in[9];
    const float* lb2  = (const float*)d_in[10];
    const int*   x    = (const int*)d_in[11];
    const int*   ei   = (const int*)d_in[12];
    const int*   batch= (const int*)d_in[13];
    const int* row = ei;
    const int* col = ei + EE;
    float* out = (float*)d_out;

    float *h0, *h1, *t1, *t2, *pool, *cnt, *chsum, *chsq;
    __nv_bfloat16 *Bh, *Bl;
    cudaGetSymbolAddress((void**)&h0, g_h0);
    cudaGetSymbolAddress((void**)&h1, g_h1);
    cudaGetSymbolAddress((void**)&t1, g_t1);
    cudaGetSymbolAddress((void**)&t2, g_t2);
    cudaGetSymbolAddress((void**)&pool, g_pool);
    cudaGetSymbolAddress((void**)&cnt, g_cnt);
    cudaGetSymbolAddress((void**)&chsum, g_chsum);
    cudaGetSymbolAddress((void**)&chsq, g_chsq);
    cudaGetSymbolAddress((void**)&Bh, g_Bh);
    cudaGetSymbolAddress((void**)&Bl, g_Bl);

    const int GEMM_SMEM = 2 * STAGE;   // 81920 B, 2 CTAs/SM
    cudaFuncSetAttribute(k_gemm, cudaFuncAttributeMaxDynamicSharedMemorySize, GEMM_SMEM);

    const int NB = (NN + 255) / 256;
    const int SPMV_B = (NN * 32 + 255) / 256;   // one warp per row
    const int MM_B = (NN + 127) / 128;          // 391 tiles

    // fused CSR build + embedding + both weight folds
    k_csr<<<CSRB, 256>>>(row, col);
    k_embed<<<NN, 128>>>(atom_emb, x);
    k_prepB2<<<256, 384>>>(W1, W3);

    // conv1: t1 = L h0, t2 = L t1 (Cheb fix-up folded into weights)
    k_spmv<<<SPMV_B, 256>>>(h0, t1);
    k_spmv<<<SPMV_B, 256>>>(t1, t2);
    k_gemm<<<MM_B, 256, GEMM_SMEM>>>(h0, t1, t2, Bh[0] ? Bh : Bh, Bl, b1, h1);

    // conv2 (conv3 weights), writes into h0
    k_spmv<<<SPMV_B, 256>>>(h1, t1);
    k_spmv<<<SPMV_B, 256>>>(t1, t2);
    k_gemm<<<MM_B, 256, GEMM_SMEM>>>(h1, t1, t2, Bh + (size_t)CC * 384,
                                     Bl + (size_t)CC * 384, b3, h0);

    // BN stats + pooling (R7-proven tail); BN affine applied post-pool
    k_zero4<<<(GG * CC / 4 + 255) / 256, 256>>>(pool, GG * CC / 4);
    k_zero4<<<1, 128>>>(cnt, GG / 4);
    k_zero4<<<1, 32>>>(chsum, CC / 4);
    k_zero4<<<1, 32>>>(chsq, CC / 4);
    k_cnt<<<NB, 256>>>(batch);
    k_statspool<<<(NN + 127) / 128, 128>>>(h0, batch);
    k_bnprep<<<1, 128>>>(gam, bet);

    // head MLP
    k_mlp<<<2, 256>>>(lw1, lb1, lw2, lb2, out);
}